// round 12
// baseline (speedup 1.0000x reference)
#include <cuda_runtime.h>
#include <cuda_bf16.h>
#include <cstdint>

#define LL 4
#define BB 8
#define PHH 37
#define PWW 37
#define PP 1369
#define DD 1024
#define JJ 768
#define HH 518
#define WWW 518
#define BP (BB*PP)        // 10952
#define NLB (LL*BB)       // 32
#define NELEM (PP*DD)     // 1401856
#define NRT 11            // row tiles per image (ceil(1369/128))
#define NCT 11

// ---------------- scratch (static device memory only) ----------------
__device__ float          g_norm[(size_t)LL*BB*PP*DD];   // ~179 MB
__device__ __nv_bfloat16  g_X   [(size_t)LL*BB*PP*DD];   // ~90 MB (reused per r)
__device__ unsigned       g_maxenc[LL*BB*PP*BB];         // encoded max-dot
__device__ float          g_scores[BB*PP];
__device__ float2         g_part[NLB][16];
__device__ float          g_mu[NLB];
__device__ float          g_rstd[NLB];

// order-preserving float <-> uint encoding (for atomicMax on floats incl. negatives)
__device__ __forceinline__ unsigned fenc(float f){
    unsigned u = __float_as_uint(f);
    return (u & 0x80000000u) ? ~u : (u | 0x80000000u);
}
__device__ __forceinline__ float fdec(unsigned e){
    unsigned u = (e & 0x80000000u) ? (e & 0x7fffffffu) : ~e;
    return __uint_as_float(u);
}

__device__ __forceinline__ void cpasync16(void* sdst, const void* gsrc, int sz){
    unsigned sa = (unsigned)__cvta_generic_to_shared(sdst);
    asm volatile("cp.async.cg.shared.global [%0], [%1], 16, %2;\n"
                 :: "r"(sa), "l"(gsrc), "r"(sz) : "memory");
}

// ---------------- trivial init kernels ----------------
__global__ void zero_scores_kernel(){
    int t = blockIdx.x*256 + threadIdx.x;
    if (t < BB*PP) g_scores[t] = 0.f;
}
__global__ void clear_maxenc_kernel(){
    int t = blockIdx.x*256 + threadIdx.x;
    if (t < LL*BB*PP*BB) g_maxenc[t] = 0u;
}

// ---------------- LayerNorm over (P,D) per (l,b) ----------------
__global__ void ln_part_kernel(const float* __restrict__ x){
    int lb = blockIdx.y, ch = blockIdx.x, tid = threadIdx.x;
    const int chunk = NELEM/16;           // 87616
    const float* base = x + (size_t)lb*NELEM + (size_t)ch*chunk;
    float s = 0.f, ss = 0.f;
    for (int t = tid; t < chunk; t += 256){ float v = base[t]; s += v; ss += v*v; }
    __shared__ float rs[256], rq[256];
    rs[tid]=s; rq[tid]=ss; __syncthreads();
    for (int o=128;o>0;o>>=1){ if(tid<o){ rs[tid]+=rs[tid+o]; rq[tid]+=rq[tid+o]; } __syncthreads(); }
    if (tid==0) g_part[lb][ch] = make_float2(rs[0], rq[0]);
}
__global__ void ln_fin_kernel(){
    int lb = threadIdx.x;
    if (lb < NLB){
        float s=0.f, ss=0.f;
        for (int c=0;c<16;c++){ float2 v=g_part[lb][c]; s+=v.x; ss+=v.y; }
        const float Nf = (float)NELEM;
        float mu = s/Nf;
        float var = ss/Nf - mu*mu;
        g_mu[lb]=mu; g_rstd[lb]=rsqrtf(var + 1e-5f);
    }
}
__global__ void ln_apply_kernel(const float* __restrict__ x){
    int lb = blockIdx.y;
    int idx = blockIdx.x*256 + threadIdx.x;
    if (idx < NELEM){
        size_t o = (size_t)lb*NELEM + idx;
        g_norm[o] = (x[o] - g_mu[lb]) * g_rstd[lb];
    }
}

// ---------------- box pooling (zero-padded, /r^2) + L2 normalize -> bf16 ----------------
__global__ void __launch_bounds__(128) pool_norm_kernel(int r){
    int bid = blockIdx.x;                 // l*B*P + b*P + p
    int p  = bid % PP;
    int lb = bid / PP;
    int y = p / PWW, x = p % PWW;
    int pad = r >> 1;
    const float* base = g_norm + (size_t)lb*PP*DD;
    float v[8];
    #pragma unroll
    for (int j=0;j<8;j++) v[j]=0.f;
    for (int dy=-pad; dy<=pad; dy++){
        int yy = y+dy; if (yy<0 || yy>=PHH) continue;
        for (int dx=-pad; dx<=pad; dx++){
            int xx = x+dx; if (xx<0 || xx>=PWW) continue;
            const float* src = base + (size_t)(yy*PWW+xx)*DD + threadIdx.x;
            #pragma unroll
            for (int j=0;j<8;j++) v[j] += src[j*128];
        }
    }
    float inv_rr = 1.f/(float)(r*r);
    float s = 0.f;
    #pragma unroll
    for (int j=0;j<8;j++){ v[j]*=inv_rr; s += v[j]*v[j]; }
    for (int o=16;o>0;o>>=1) s += __shfl_xor_sync(0xffffffffu, s, o);
    __shared__ float ws[4];
    if ((threadIdx.x&31)==0) ws[threadIdx.x>>5]=s;
    __syncthreads();
    float rn = rsqrtf(ws[0]+ws[1]+ws[2]+ws[3]);
    __nv_bfloat16* dst = g_X + (size_t)bid*DD;
    #pragma unroll
    for (int j=0;j<8;j++) dst[threadIdx.x + j*128] = __float2bfloat16(v[j]*rn);
}

// ---------------- GEMM (X X^T block) fused with max-over-cols reduction ----------------
// grid: x = rt*11+ct (121), y = b-enum (7, skipping b==i), z = l*8+i (32). 256 threads.
__global__ void __launch_bounds__(256,2) gemm_max_kernel(){
    const int l = blockIdx.z >> 3;
    const int i = blockIdx.z & 7;
    int bb = blockIdx.y;
    const int b = bb + (bb >= i ? 1 : 0);
    const int rt = blockIdx.x / NCT, ct = blockIdx.x % NCT;
    const int rowBase = rt*128, colBase = ct*128;
    const int validRows = min(128, PP - rowBase);
    const int validCols = min(128, PP - colBase);
    const __nv_bfloat16* Aptr = g_X + ((size_t)l*BP + (size_t)i*PP + rowBase)*DD;
    const __nv_bfloat16* Bptr = g_X + ((size_t)l*BP + (size_t)b*PP + colBase)*DD;

    __shared__ __align__(16) __nv_bfloat16 sA[2][128][40];
    __shared__ __align__(16) __nv_bfloat16 sB[2][128][40];
    __shared__ float sPart[128][4];

    const int tid  = threadIdx.x;
    const int warp = tid >> 5, lane = tid & 31;
    const int wm = warp >> 2, wn = warp & 3;

    auto loadTile = [&](int stg, int k0){
        #pragma unroll
        for (int it=0; it<4; ++it){
            int v = tid + it*256;
            if (v < 512){
                int row = v>>2, c = v&3;
                bool ok = row < validRows;
                const __nv_bfloat16* g = Aptr + (size_t)row*DD + k0 + c*8;
                cpasync16(&sA[stg][row][c*8], ok ? (const void*)g : (const void*)Aptr, ok?16:0);
            } else {
                int v2 = v-512;
                int row = v2>>2, c = v2&3;
                bool ok = row < validCols;
                const __nv_bfloat16* g = Bptr + (size_t)row*DD + k0 + c*8;
                cpasync16(&sB[stg][row][c*8], ok ? (const void*)g : (const void*)Bptr, ok?16:0);
            }
        }
    };

    float acc[4][4][4];
    #pragma unroll
    for (int a=0;a<4;a++)
        #pragma unroll
        for (int c=0;c<4;c++)
            #pragma unroll
            for (int e=0;e<4;e++) acc[a][c][e]=0.f;

    const int jj = lane>>3, rr = lane&7;

    auto computeTile = [&](int stg){
        #pragma unroll
        for (int ks=0; ks<32; ks+=16){
            uint32_t af[4][4];
            #pragma unroll
            for (int mi=0; mi<4; mi++){
                unsigned sa = (unsigned)__cvta_generic_to_shared(
                    &sA[stg][wm*64 + mi*16 + (jj&1)*8 + rr][ks + (jj>>1)*8]);
                asm volatile("ldmatrix.sync.aligned.m8n8.x4.shared.b16 {%0,%1,%2,%3},[%4];"
                    : "=r"(af[mi][0]),"=r"(af[mi][1]),"=r"(af[mi][2]),"=r"(af[mi][3]) : "r"(sa));
            }
            uint32_t bf[4][2];
            #pragma unroll
            for (int pr=0; pr<2; pr++){
                unsigned sa = (unsigned)__cvta_generic_to_shared(
                    &sB[stg][wn*32 + pr*16 + (jj>>1)*8 + rr][ks + (jj&1)*8]);
                uint32_t r0,r1,r2,r3;
                asm volatile("ldmatrix.sync.aligned.m8n8.x4.shared.b16 {%0,%1,%2,%3},[%4];"
                    : "=r"(r0),"=r"(r1),"=r"(r2),"=r"(r3) : "r"(sa));
                bf[pr*2][0]=r0; bf[pr*2][1]=r1; bf[pr*2+1][0]=r2; bf[pr*2+1][1]=r3;
            }
            #pragma unroll
            for (int mi=0; mi<4; mi++)
                #pragma unroll
                for (int ni=0; ni<4; ni++)
                    asm volatile("mma.sync.aligned.m16n8k16.row.col.f32.bf16.bf16.f32 "
                        "{%0,%1,%2,%3},{%4,%5,%6,%7},{%8,%9},{%0,%1,%2,%3};"
                        : "+f"(acc[mi][ni][0]),"+f"(acc[mi][ni][1]),"+f"(acc[mi][ni][2]),"+f"(acc[mi][ni][3])
                        : "r"(af[mi][0]),"r"(af[mi][1]),"r"(af[mi][2]),"r"(af[mi][3]),
                          "r"(bf[ni][0]),"r"(bf[ni][1]));
        }
    };

    const int NKT = DD/32;  // 32
    loadTile(0, 0);  asm volatile("cp.async.commit_group;" ::: "memory");
    loadTile(1, 32); asm volatile("cp.async.commit_group;" ::: "memory");
    #pragma unroll 1
    for (int kt=0; kt<NKT; ++kt){
        if (kt < NKT-1) asm volatile("cp.async.wait_group 1;" ::: "memory");
        else            asm volatile("cp.async.wait_group 0;" ::: "memory");
        __syncthreads();
        computeTile(kt & 1);
        __syncthreads();
        if (kt+2 < NKT){
            loadTile(kt & 1, (kt+2)*32);
            asm volatile("cp.async.commit_group;" ::: "memory");
        }
    }

    // epilogue: per-row max over valid cols
    #pragma unroll
    for (int mi=0; mi<4; mi++){
        float m0 = -1e30f, m1 = -1e30f;
        #pragma unroll
        for (int ni=0; ni<4; ni++){
            int colb = wn*32 + ni*8 + (lane&3)*2;
            if (colb     < validCols){ m0 = fmaxf(m0, acc[mi][ni][0]); m1 = fmaxf(m1, acc[mi][ni][2]); }
            if (colb + 1 < validCols){ m0 = fmaxf(m0, acc[mi][ni][1]); m1 = fmaxf(m1, acc[mi][ni][3]); }
        }
        m0 = fmaxf(m0, __shfl_xor_sync(0xffffffffu, m0, 1));
        m0 = fmaxf(m0, __shfl_xor_sync(0xffffffffu, m0, 2));
        m1 = fmaxf(m1, __shfl_xor_sync(0xffffffffu, m1, 1));
        m1 = fmaxf(m1, __shfl_xor_sync(0xffffffffu, m1, 2));
        if ((lane&3)==0){
            int g = lane>>2;
            sPart[wm*64 + mi*16 + g    ][wn] = m0;
            sPart[wm*64 + mi*16 + g + 8][wn] = m1;
        }
    }
    __syncthreads();
    if (tid < 128 && tid < validRows){
        float mx = fmaxf(fmaxf(sPart[tid][0], sPart[tid][1]),
                         fmaxf(sPart[tid][2], sPart[tid][3]));
        size_t o = ((size_t)((l*8 + i)*PP) + rowBase + tid)*8 + b;
        atomicMax(&g_maxenc[o], fenc(mx));
    }
}

// ---------------- per-(i,p): dist from maxdot, top-2-smallest mean, accumulate ----------------
__global__ void scores_acc_kernel(){
    int idx = blockIdx.x*256 + threadIdx.x;
    if (idx >= BB*PP) return;
    int i = idx / PP, p = idx % PP;
    float acc = 0.f;
    #pragma unroll
    for (int l=0;l<LL;l++){
        float b1 = 1e30f, b2 = 1e30f;
        const unsigned* mp = g_maxenc + ((size_t)(l*8 + i)*PP + p)*8;
        #pragma unroll
        for (int b=0;b<8;b++){
            if (b == i) continue;
            float dot = fdec(mp[b]);
            float dist = sqrtf(fmaxf(2.f - 2.f*dot, 1e-12f));
            if (dist < b1){ b2=b1; b1=dist; } else if (dist < b2){ b2=dist; }
        }
        acc += 0.5f*(b1+b2);
    }
    g_scores[idx] += acc * (1.f/12.f);   // mean over 4 layers x 3 radii
}

// ---------------- cls head: sim top-k weighted scores ----------------
__global__ void final_kernel(const float* __restrict__ cls, float* __restrict__ out8){
    __shared__ float sim[8][8];
    __shared__ float inv[8];
    __shared__ float img[8];
    __shared__ float red[256];
    int tid = threadIdx.x;
    for (int i=0;i<8;i++){
        float m = -1e30f;
        for (int p=tid; p<PP; p+=256) m = fmaxf(m, g_scores[i*PP + p]);
        red[tid] = m; __syncthreads();
        for (int o=128;o>0;o>>=1){ if (tid<o) red[tid]=fmaxf(red[tid],red[tid+o]); __syncthreads(); }
        if (tid==0) img[i]=red[0];
        __syncthreads();
    }
    if (tid < 8){
        float s=0.f;
        for (int d=0; d<JJ; d++){ float v = cls[tid*JJ+d]; s += v*v; }
        inv[tid] = rsqrtf(s);
    }
    __syncthreads();
    if (tid < 64){
        int a = tid>>3, c = tid&7;
        float s=0.f;
        for (int d=0; d<JJ; d++) s += cls[a*JJ+d]*cls[c*JJ+d];
        sim[a][c] = s * inv[a] * inv[c];
    }
    __syncthreads();
    if (tid < 8){
        float t1=-1e30f,t2=-1e30f,t3=-1e30f; int x1=0,x2=0,x3=0;
        for (int j=0;j<8;j++){
            float v = sim[tid][j];
            if (v > t1){ t3=t2;x3=x2; t2=t1;x2=x1; t1=v;x1=j; }
            else if (v > t2){ t3=t2;x3=x2; t2=v;x2=j; }
            else if (v > t3){ t3=v;x3=j; }
        }
        float f = 0.f;
        f += (t1*img[x1]) / t1;
        f += (t1*img[x1] + t2*img[x2]) / (t1+t2);
        f += (t1*img[x1] + t2*img[x2] + t3*img[x3]) / (t1+t2+t3);
        out8[tid] = f * (1.f/3.f);
    }
}

// ---------------- bilinear upsample 37x37 -> 518x518 ----------------
__global__ void pixel_kernel(float* __restrict__ out){
    int idx = blockIdx.x*256 + threadIdx.x;
    const int TOT = BB*HH*WWW;
    if (idx >= TOT) return;
    int b = idx / (HH*WWW);
    int rem = idx % (HH*WWW);
    int Y = rem / WWW, X = rem % WWW;
    const float sc = (float)((double)(PHH-1)/(double)(HH-1));
    float py = (float)Y * sc;
    float px = (float)X * sc;
    int y0 = (int)floorf(py); y0 = min(max(y0,0), PHH-1); int y1 = min(y0+1, PHH-1);
    int x0 = (int)floorf(px); x0 = min(max(x0,0), PWW-1); int x1 = min(x0+1, PWW-1);
    float wy = py - (float)y0, wx = px - (float)x0;
    const float* s = g_scores + (size_t)b*PP;
    float v00 = s[y0*PWW+x0], v01 = s[y0*PWW+x1];
    float v10 = s[y1*PWW+x0], v11 = s[y1*PWW+x1];
    out[idx] = (1.f-wy)*((1.f-wx)*v00 + wx*v01) + wy*((1.f-wx)*v10 + wx*v11);
}

// ---------------- launch ----------------
extern "C" void kernel_launch(void* const* d_in, const int* in_sizes, int n_in,
                              void* d_out, int out_size){
    const float* feats = (const float*)d_in[0];
    const float* cls   = (const float*)d_in[1];
    float* out = (float*)d_out;

    zero_scores_kernel<<<(BB*PP + 255)/256, 256>>>();
    ln_part_kernel<<<dim3(16, NLB), 256>>>(feats);
    ln_fin_kernel<<<1, 32>>>();
    ln_apply_kernel<<<dim3((NELEM + 255)/256, NLB), 256>>>(feats);

    const int rlist[3] = {1, 3, 5};
    for (int ri = 0; ri < 3; ++ri){
        pool_norm_kernel<<<LL*BB*PP, 128>>>(rlist[ri]);
        clear_maxenc_kernel<<<(LL*BB*PP*BB + 255)/256, 256>>>();
        gemm_max_kernel<<<dim3(NRT*NCT, BB-1, NLB), 256>>>();
        scores_acc_kernel<<<(BB*PP + 255)/256, 256>>>();
    }

    final_kernel<<<1, 256>>>(cls, out);
    pixel_kernel<<<(BB*HH*WWW + 255)/256, 256>>>(out + 8);
}

// round 14
// speedup vs baseline: 1.8353x; 1.8353x over previous
#include <cuda_runtime.h>
#include <cuda_bf16.h>
#include <cstdint>

#define LL 4
#define BB 8
#define PHH 37
#define PWW 37
#define PP 1369
#define DD 1024
#define JJ 768
#define HH 518
#define WWW 518
#define BP (BB*PP)        // 10952
#define NLB (LL*BB)       // 32
#define NELEM (PP*DD)     // 1401856
#define NRT 11            // row tiles per image (ceil(1369/128))
#define NCT 11
#define NPAIRS 28         // unordered image pairs (8 choose 2)

// ---------------- scratch (static device memory only) ----------------
__device__ float          g_norm[(size_t)LL*BB*PP*DD];   // ~179 MB
__device__ __nv_bfloat16  g_X   [(size_t)LL*BB*PP*DD];   // ~90 MB (reused per r)
__device__ unsigned       g_maxenc[LL*BB*PP*BB];         // encoded max-dot
__device__ float          g_scores[BB*PP];
__device__ float2         g_part[NLB][16];
__device__ float          g_mu[NLB];
__device__ float          g_rstd[NLB];

// order-preserving float <-> uint encoding (for atomicMax on floats incl. negatives)
__device__ __forceinline__ unsigned fenc(float f){
    unsigned u = __float_as_uint(f);
    return (u & 0x80000000u) ? ~u : (u | 0x80000000u);
}
__device__ __forceinline__ float fdec(unsigned e){
    unsigned u = (e & 0x80000000u) ? (e & 0x7fffffffu) : ~e;
    return __uint_as_float(u);
}

__device__ __forceinline__ void cpasync16(void* sdst, const void* gsrc, int sz){
    unsigned sa = (unsigned)__cvta_generic_to_shared(sdst);
    asm volatile("cp.async.cg.shared.global [%0], [%1], 16, %2;\n"
                 :: "r"(sa), "l"(gsrc), "r"(sz) : "memory");
}

// ---------------- trivial init kernels ----------------
__global__ void zero_scores_kernel(){
    int t = blockIdx.x*256 + threadIdx.x;
    if (t < BB*PP) g_scores[t] = 0.f;
}
__global__ void clear_maxenc_kernel(){
    int t = blockIdx.x*256 + threadIdx.x;
    if (t < LL*BB*PP*BB) g_maxenc[t] = 0u;
}

// ---------------- LayerNorm over (P,D) per (l,b) ----------------
__global__ void ln_part_kernel(const float* __restrict__ x){
    int lb = blockIdx.y, ch = blockIdx.x, tid = threadIdx.x;
    const int chunk = NELEM/16;           // 87616
    const float* base = x + (size_t)lb*NELEM + (size_t)ch*chunk;
    float s = 0.f, ss = 0.f;
    for (int t = tid; t < chunk; t += 256){ float v = base[t]; s += v; ss += v*v; }
    __shared__ float rs[256], rq[256];
    rs[tid]=s; rq[tid]=ss; __syncthreads();
    for (int o=128;o>0;o>>=1){ if(tid<o){ rs[tid]+=rs[tid+o]; rq[tid]+=rq[tid+o]; } __syncthreads(); }
    if (tid==0) g_part[lb][ch] = make_float2(rs[0], rq[0]);
}
__global__ void ln_fin_kernel(){
    int lb = threadIdx.x;
    if (lb < NLB){
        float s=0.f, ss=0.f;
        for (int c=0;c<16;c++){ float2 v=g_part[lb][c]; s+=v.x; ss+=v.y; }
        const float Nf = (float)NELEM;
        float mu = s/Nf;
        float var = ss/Nf - mu*mu;
        g_mu[lb]=mu; g_rstd[lb]=rsqrtf(var + 1e-5f);
    }
}
__global__ void ln_apply_kernel(const float* __restrict__ x){
    int lb = blockIdx.y;
    int idx = blockIdx.x*256 + threadIdx.x;
    if (idx < NELEM){
        size_t o = (size_t)lb*NELEM + idx;
        g_norm[o] = (x[o] - g_mu[lb]) * g_rstd[lb];
    }
}

// ---------------- box pooling (zero-padded, /r^2) + L2 normalize -> bf16 ----------------
__global__ void __launch_bounds__(128) pool_norm_kernel(int r){
    int bid = blockIdx.x;                 // l*B*P + b*P + p
    int p  = bid % PP;
    int lb = bid / PP;
    int y = p / PWW, x = p % PWW;
    int pad = r >> 1;
    const float* base = g_norm + (size_t)lb*PP*DD;
    float v[8];
    #pragma unroll
    for (int j=0;j<8;j++) v[j]=0.f;
    for (int dy=-pad; dy<=pad; dy++){
        int yy = y+dy; if (yy<0 || yy>=PHH) continue;
        for (int dx=-pad; dx<=pad; dx++){
            int xx = x+dx; if (xx<0 || xx>=PWW) continue;
            const float* src = base + (size_t)(yy*PWW+xx)*DD + threadIdx.x;
            #pragma unroll
            for (int j=0;j<8;j++) v[j] += src[j*128];
        }
    }
    float inv_rr = 1.f/(float)(r*r);
    float s = 0.f;
    #pragma unroll
    for (int j=0;j<8;j++){ v[j]*=inv_rr; s += v[j]*v[j]; }
    for (int o=16;o>0;o>>=1) s += __shfl_xor_sync(0xffffffffu, s, o);
    __shared__ float ws[4];
    if ((threadIdx.x&31)==0) ws[threadIdx.x>>5]=s;
    __syncthreads();
    float rn = rsqrtf(ws[0]+ws[1]+ws[2]+ws[3]);
    __nv_bfloat16* dst = g_X + (size_t)bid*DD;
    #pragma unroll
    for (int j=0;j<8;j++) dst[threadIdx.x + j*128] = __float2bfloat16(v[j]*rn);
}

// ---------------- GEMM (X X^T block) fused with row-max AND col-max ----------------
// Unordered pairs i<b: row-max of G(i,b) feeds image i's mins vs b; col-max feeds b vs i.
// grid: x = rt*11+ct (121), y = pair (28), z = l (4). 256 threads.
__global__ void __launch_bounds__(256,2) gemm_max_kernel(){
    const int l = blockIdx.z;
    // decode unordered pair index -> (i, b) with i < b
    int rem = blockIdx.y;
    int i = 0;
    while (rem >= 7 - i){ rem -= 7 - i; i++; }
    const int b = i + 1 + rem;

    const int rt = blockIdx.x / NCT, ct = blockIdx.x % NCT;
    const int rowBase = rt*128, colBase = ct*128;
    const int validRows = min(128, PP - rowBase);
    const int validCols = min(128, PP - colBase);
    const __nv_bfloat16* Aptr = g_X + ((size_t)l*BP + (size_t)i*PP + rowBase)*DD;
    const __nv_bfloat16* Bptr = g_X + ((size_t)l*BP + (size_t)b*PP + colBase)*DD;

    __shared__ __align__(16) __nv_bfloat16 sA[2][128][40];
    __shared__ __align__(16) __nv_bfloat16 sB[2][128][40];
    __shared__ float sPart[128][4];
    __shared__ float sCol[128][2];

    const int tid  = threadIdx.x;
    const int warp = tid >> 5, lane = tid & 31;
    const int wm = warp >> 2, wn = warp & 3;

    auto loadTile = [&](int stg, int k0){
        #pragma unroll
        for (int it=0; it<4; ++it){
            int v = tid + it*256;
            if (v < 512){
                int row = v>>2, c = v&3;
                bool ok = row < validRows;
                const __nv_bfloat16* g = Aptr + (size_t)row*DD + k0 + c*8;
                cpasync16(&sA[stg][row][c*8], ok ? (const void*)g : (const void*)Aptr, ok?16:0);
            } else {
                int v2 = v-512;
                int row = v2>>2, c = v2&3;
                bool ok = row < validCols;
                const __nv_bfloat16* g = Bptr + (size_t)row*DD + k0 + c*8;
                cpasync16(&sB[stg][row][c*8], ok ? (const void*)g : (const void*)Bptr, ok?16:0);
            }
        }
    };

    float acc[4][4][4];
    #pragma unroll
    for (int a=0;a<4;a++)
        #pragma unroll
        for (int c=0;c<4;c++)
            #pragma unroll
            for (int e=0;e<4;e++) acc[a][c][e]=0.f;

    const int jj = lane>>3, rr = lane&7;

    auto computeTile = [&](int stg){
        #pragma unroll
        for (int ks=0; ks<32; ks+=16){
            uint32_t af[4][4];
            #pragma unroll
            for (int mi=0; mi<4; mi++){
                unsigned sa = (unsigned)__cvta_generic_to_shared(
                    &sA[stg][wm*64 + mi*16 + (jj&1)*8 + rr][ks + (jj>>1)*8]);
                asm volatile("ldmatrix.sync.aligned.m8n8.x4.shared.b16 {%0,%1,%2,%3},[%4];"
                    : "=r"(af[mi][0]),"=r"(af[mi][1]),"=r"(af[mi][2]),"=r"(af[mi][3]) : "r"(sa));
            }
            uint32_t bf[4][2];
            #pragma unroll
            for (int pr=0; pr<2; pr++){
                unsigned sa = (unsigned)__cvta_generic_to_shared(
                    &sB[stg][wn*32 + pr*16 + (jj>>1)*8 + rr][ks + (jj&1)*8]);
                uint32_t r0,r1,r2,r3;
                asm volatile("ldmatrix.sync.aligned.m8n8.x4.shared.b16 {%0,%1,%2,%3},[%4];"
                    : "=r"(r0),"=r"(r1),"=r"(r2),"=r"(r3) : "r"(sa));
                bf[pr*2][0]=r0; bf[pr*2][1]=r1; bf[pr*2+1][0]=r2; bf[pr*2+1][1]=r3;
            }
            #pragma unroll
            for (int mi=0; mi<4; mi++)
                #pragma unroll
                for (int ni=0; ni<4; ni++)
                    asm volatile("mma.sync.aligned.m16n8k16.row.col.f32.bf16.bf16.f32 "
                        "{%0,%1,%2,%3},{%4,%5,%6,%7},{%8,%9},{%0,%1,%2,%3};"
                        : "+f"(acc[mi][ni][0]),"+f"(acc[mi][ni][1]),"+f"(acc[mi][ni][2]),"+f"(acc[mi][ni][3])
                        : "r"(af[mi][0]),"r"(af[mi][1]),"r"(af[mi][2]),"r"(af[mi][3]),
                          "r"(bf[ni][0]),"r"(bf[ni][1]));
        }
    };

    const int NKT = DD/32;  // 32
    loadTile(0, 0);  asm volatile("cp.async.commit_group;" ::: "memory");
    loadTile(1, 32); asm volatile("cp.async.commit_group;" ::: "memory");
    #pragma unroll 1
    for (int kt=0; kt<NKT; ++kt){
        if (kt < NKT-1) asm volatile("cp.async.wait_group 1;" ::: "memory");
        else            asm volatile("cp.async.wait_group 0;" ::: "memory");
        __syncthreads();
        computeTile(kt & 1);
        __syncthreads();
        if (kt+2 < NKT){
            loadTile(kt & 1, (kt+2)*32);
            asm volatile("cp.async.commit_group;" ::: "memory");
        }
    }

    // ---- epilogue 1: per-row max over valid cols ----
    #pragma unroll
    for (int mi=0; mi<4; mi++){
        float m0 = -1e30f, m1 = -1e30f;
        #pragma unroll
        for (int ni=0; ni<4; ni++){
            int colb = wn*32 + ni*8 + (lane&3)*2;
            if (colb     < validCols){ m0 = fmaxf(m0, acc[mi][ni][0]); m1 = fmaxf(m1, acc[mi][ni][2]); }
            if (colb + 1 < validCols){ m0 = fmaxf(m0, acc[mi][ni][1]); m1 = fmaxf(m1, acc[mi][ni][3]); }
        }
        m0 = fmaxf(m0, __shfl_xor_sync(0xffffffffu, m0, 1));
        m0 = fmaxf(m0, __shfl_xor_sync(0xffffffffu, m0, 2));
        m1 = fmaxf(m1, __shfl_xor_sync(0xffffffffu, m1, 1));
        m1 = fmaxf(m1, __shfl_xor_sync(0xffffffffu, m1, 2));
        if ((lane&3)==0){
            int g = lane>>2;
            sPart[wm*64 + mi*16 + g    ][wn] = m0;
            sPart[wm*64 + mi*16 + g + 8][wn] = m1;
        }
    }

    // ---- epilogue 2: per-col max over valid rows ----
    // thread holds, per ni: cols c0 = wn*32+ni*8+(lane&3)*2, c1 = c0+1
    // rows: wm*64 + mi*16 + grp (elems 0,1) and +8 (elems 2,3); mask rows >= validRows
    {
        const int grp = lane >> 2;
        #pragma unroll
        for (int ni=0; ni<4; ni++){
            float c0 = -1e30f, c1 = -1e30f;
            #pragma unroll
            for (int mi=0; mi<4; mi++){
                int r0 = wm*64 + mi*16 + grp;
                int r1 = r0 + 8;
                if (r0 < validRows){ c0 = fmaxf(c0, acc[mi][ni][0]); c1 = fmaxf(c1, acc[mi][ni][1]); }
                if (r1 < validRows){ c0 = fmaxf(c0, acc[mi][ni][2]); c1 = fmaxf(c1, acc[mi][ni][3]); }
            }
            // reduce across the 8 row-groups (lanes sharing lane&3)
            #pragma unroll
            for (int o=4;o<32;o<<=1){
                c0 = fmaxf(c0, __shfl_xor_sync(0xffffffffu, c0, o));
                c1 = fmaxf(c1, __shfl_xor_sync(0xffffffffu, c1, o));
            }
            if (grp == 0){
                int col = wn*32 + ni*8 + (lane&3)*2;
                sCol[col  ][wm] = c0;
                sCol[col+1][wm] = c1;
            }
        }
    }
    __syncthreads();

    if (tid < 128){
        if (tid < validRows){
            float mx = fmaxf(fmaxf(sPart[tid][0], sPart[tid][1]),
                             fmaxf(sPart[tid][2], sPart[tid][3]));
            size_t o = ((size_t)((l*8 + i)*PP) + rowBase + tid)*8 + b;
            atomicMax(&g_maxenc[o], fenc(mx));
        }
        if (tid < validCols){
            float mx = fmaxf(sCol[tid][0], sCol[tid][1]);
            size_t o = ((size_t)((l*8 + b)*PP) + colBase + tid)*8 + i;
            atomicMax(&g_maxenc[o], fenc(mx));
        }
    }
}

// ---------------- per-(i,p): dist from maxdot, top-2-smallest mean, accumulate ----------------
__global__ void scores_acc_kernel(){
    int idx = blockIdx.x*256 + threadIdx.x;
    if (idx >= BB*PP) return;
    int i = idx / PP, p = idx % PP;
    float acc = 0.f;
    #pragma unroll
    for (int l=0;l<LL;l++){
        float b1 = 1e30f, b2 = 1e30f;
        const unsigned* mp = g_maxenc + ((size_t)(l*8 + i)*PP + p)*8;
        #pragma unroll
        for (int b=0;b<8;b++){
            if (b == i) continue;
            float dot = fdec(mp[b]);
            float dist = sqrtf(fmaxf(2.f - 2.f*dot, 1e-12f));
            if (dist < b1){ b2=b1; b1=dist; } else if (dist < b2){ b2=dist; }
        }
        acc += 0.5f*(b1+b2);
    }
    g_scores[idx] += acc * (1.f/12.f);   // mean over 4 layers x 3 radii
}

// ---------------- cls head: sim top-k weighted scores ----------------
__global__ void final_kernel(const float* __restrict__ cls, float* __restrict__ out8){
    __shared__ float sim[8][8];
    __shared__ float inv[8];
    __shared__ float img[8];
    __shared__ float red[256];
    int tid = threadIdx.x;
    for (int i=0;i<8;i++){
        float m = -1e30f;
        for (int p=tid; p<PP; p+=256) m = fmaxf(m, g_scores[i*PP + p]);
        red[tid] = m; __syncthreads();
        for (int o=128;o>0;o>>=1){ if (tid<o) red[tid]=fmaxf(red[tid],red[tid+o]); __syncthreads(); }
        if (tid==0) img[i]=red[0];
        __syncthreads();
    }
    if (tid < 8){
        float s=0.f;
        for (int d=0; d<JJ; d++){ float v = cls[tid*JJ+d]; s += v*v; }
        inv[tid] = rsqrtf(s);
    }
    __syncthreads();
    if (tid < 64){
        int a = tid>>3, c = tid&7;
        float s=0.f;
        for (int d=0; d<JJ; d++) s += cls[a*JJ+d]*cls[c*JJ+d];
        sim[a][c] = s * inv[a] * inv[c];
    }
    __syncthreads();
    if (tid < 8){
        float t1=-1e30f,t2=-1e30f,t3=-1e30f; int x1=0,x2=0,x3=0;
        for (int j=0;j<8;j++){
            float v = sim[tid][j];
            if (v > t1){ t3=t2;x3=x2; t2=t1;x2=x1; t1=v;x1=j; }
            else if (v > t2){ t3=t2;x3=x2; t2=v;x2=j; }
            else if (v > t3){ t3=v;x3=j; }
        }
        float f = 0.f;
        f += (t1*img[x1]) / t1;
        f += (t1*img[x1] + t2*img[x2]) / (t1+t2);
        f += (t1*img[x1] + t2*img[x2] + t3*img[x3]) / (t1+t2+t3);
        out8[tid] = f * (1.f/3.f);
    }
}

// ---------------- bilinear upsample 37x37 -> 518x518 ----------------
__global__ void pixel_kernel(float* __restrict__ out){
    int idx = blockIdx.x*256 + threadIdx.x;
    const int TOT = BB*HH*WWW;
    if (idx >= TOT) return;
    int b = idx / (HH*WWW);
    int rem = idx % (HH*WWW);
    int Y = rem / WWW, X = rem % WWW;
    const float sc = (float)((double)(PHH-1)/(double)(HH-1));
    float py = (float)Y * sc;
    float px = (float)X * sc;
    int y0 = (int)floorf(py); y0 = min(max(y0,0), PHH-1); int y1 = min(y0+1, PHH-1);
    int x0 = (int)floorf(px); x0 = min(max(x0,0), PWW-1); int x1 = min(x0+1, PWW-1);
    float wy = py - (float)y0, wx = px - (float)x0;
    const float* s = g_scores + (size_t)b*PP;
    float v00 = s[y0*PWW+x0], v01 = s[y0*PWW+x1];
    float v10 = s[y1*PWW+x0], v11 = s[y1*PWW+x1];
    out[idx] = (1.f-wy)*((1.f-wx)*v00 + wx*v01) + wy*((1.f-wx)*v10 + wx*v11);
}

// ---------------- launch ----------------
extern "C" void kernel_launch(void* const* d_in, const int* in_sizes, int n_in,
                              void* d_out, int out_size){
    const float* feats = (const float*)d_in[0];
    const float* cls   = (const float*)d_in[1];
    float* out = (float*)d_out;

    zero_scores_kernel<<<(BB*PP + 255)/256, 256>>>();
    ln_part_kernel<<<dim3(16, NLB), 256>>>(feats);
    ln_fin_kernel<<<1, 32>>>();
    ln_apply_kernel<<<dim3((NELEM + 255)/256, NLB), 256>>>(feats);

    const int rlist[3] = {1, 3, 5};
    for (int ri = 0; ri < 3; ++ri){
        pool_norm_kernel<<<LL*BB*PP, 128>>>(rlist[ri]);
        clear_maxenc_kernel<<<(LL*BB*PP*BB + 255)/256, 256>>>();
        gemm_max_kernel<<<dim3(NRT*NCT, NPAIRS, LL), 256>>>();
        scores_acc_kernel<<<(BB*PP + 255)/256, 256>>>();
    }

    final_kernel<<<1, 256>>>(cls, out);
    pixel_kernel<<<(BB*HH*WWW + 255)/256, 256>>>(out + 8);
}